// round 1
// baseline (speedup 1.0000x reference)
#include <cuda_runtime.h>

#define NG   4096
#define WI   96
#define HI   96
#define NPIX (WI*HI)

// ---- device scratch (no allocations allowed) ----
__device__ float  g_depth[NG];
__device__ float4 g_pre[NG*3];      // unsorted per-gaussian packed data
__device__ float4 g_sorted[NG*3];   // depth-sorted per-gaussian packed data
// layout per gaussian (3 x float4):
//  [0]: ux, uy, cinv0 (=c/det), cinv1 (=-b/det)
//  [1]: cinv2 (=a/det), alpha_eff (0 if invalid), colR, colG
//  [2]: colB, -, -, -

// ============================================================
// Kernel 1: per-gaussian preprocessing
// ============================================================
__global__ void preprocess_kernel(
    const float* __restrict__ pws,
    const float* __restrict__ low_shs,
    const float* __restrict__ high_shs,
    const float* __restrict__ alphas_raw,
    const float* __restrict__ scales_raw,
    const float* __restrict__ rots_raw,
    const float* __restrict__ Rcw,
    const float* __restrict__ tcw,
    const float* __restrict__ cam,
    float* __restrict__ areas, int write_areas)
{
    int i = blockIdx.x * blockDim.x + threadIdx.x;
    if (i >= NG) return;

    float fx = cam[0], fy = cam[1], cx = cam[2], cy = cam[3];
    float R00=Rcw[0],R01=Rcw[1],R02=Rcw[2];
    float R10=Rcw[3],R11=Rcw[4],R12=Rcw[5];
    float R20=Rcw[6],R21=Rcw[7],R22=Rcw[8];
    float t0=tcw[0], t1=tcw[1], t2=tcw[2];

    float pwx = pws[3*i+0], pwy = pws[3*i+1], pwz = pws[3*i+2];

    // camera-space point
    float pcx = R00*pwx + R01*pwy + R02*pwz + t0;
    float pcy = R10*pwx + R11*pwy + R12*pwz + t1;
    float pcz = R20*pwx + R21*pwy + R22*pwz + t2;
    float depth = pcz;
    float zs = depth > 1e-6f ? depth : 1e-6f;
    float invz = 1.0f / zs;

    float ux = fx * pcx * invz + cx;
    float uy = fy * pcy * invz + cy;

    // rotation from normalized quaternion
    float qw = rots_raw[4*i+0], qx = rots_raw[4*i+1];
    float qy = rots_raw[4*i+2], qz = rots_raw[4*i+3];
    float qn = rsqrtf(qw*qw + qx*qx + qy*qy + qz*qz);
    qw*=qn; qx*=qn; qy*=qn; qz*=qn;

    float s0 = expf(scales_raw[3*i+0]);
    float s1 = expf(scales_raw[3*i+1]);
    float s2 = expf(scales_raw[3*i+2]);

    float r00 = 1.f - 2.f*(qy*qy + qz*qz), r01 = 2.f*(qx*qy - qw*qz), r02 = 2.f*(qx*qz + qw*qy);
    float r10 = 2.f*(qx*qy + qw*qz), r11 = 1.f - 2.f*(qx*qx + qz*qz), r12 = 2.f*(qy*qz - qw*qx);
    float r20 = 2.f*(qx*qz - qw*qy), r21 = 2.f*(qy*qz + qw*qx), r22 = 1.f - 2.f*(qx*qx + qy*qy);

    // M = R * diag(s)   (column-scaled)
    float m00=r00*s0, m01=r01*s1, m02=r02*s2;
    float m10=r10*s0, m11=r11*s1, m12=r12*s2;
    float m20=r20*s0, m21=r21*s1, m22=r22*s2;

    // Jacobian
    float limx = 1.3f * ((float)WI / (2.0f*fx));
    float limy = 1.3f * ((float)HI / (2.0f*fy));
    float txc = fminf(fmaxf(pcx*invz, -limx), limx) * zs;
    float tyc = fminf(fmaxf(pcy*invz, -limy), limy) * zs;
    float j00 = fx*invz,  j02 = -fx*txc*invz*invz;
    float j11 = fy*invz,  j12 = -fy*tyc*invz*invz;

    // T2 = J @ Rcw  (2x3)
    float T00 = j00*R00 + j02*R20, T01 = j00*R01 + j02*R21, T02 = j00*R02 + j02*R22;
    float T10 = j11*R10 + j12*R20, T11 = j11*R11 + j12*R21, T12 = j11*R12 + j12*R22;

    // Wm = T2 @ M  (2x3) ;  cov2d = Wm @ Wm^T
    float W00 = T00*m00 + T01*m10 + T02*m20;
    float W01 = T00*m01 + T01*m11 + T02*m21;
    float W02 = T00*m02 + T01*m12 + T02*m22;
    float W10 = T10*m00 + T11*m10 + T12*m20;
    float W11 = T10*m01 + T11*m11 + T12*m21;
    float W12 = T10*m02 + T11*m12 + T12*m22;

    float a  = W00*W00 + W01*W01 + W02*W02 + 0.3f;
    float b  = W00*W10 + W01*W11 + W02*W12;
    float cc = W10*W10 + W11*W11 + W12*W12 + 0.3f;
    float det = a*cc - b*b;
    float inv = 1.0f / det;

    float mid = 0.5f*(a + cc);
    float lam = mid + sqrtf(fmaxf(mid*mid - det, 0.1f));
    float radius = ceilf(3.0f * sqrtf(lam));

    // alpha (validity folded in: invalid -> alpha 0 -> ap 0 everywhere)
    float alpha = 1.0f / (1.0f + expf(-alphas_raw[i]));
    if (!(depth > 0.2f)) alpha = 0.0f;

    // view direction: dirs = pws - twc, twc = -(Rcw^T tcw)
    float twx = -(R00*t0 + R10*t1 + R20*t2);
    float twy = -(R01*t0 + R11*t1 + R21*t2);
    float twz = -(R02*t0 + R12*t1 + R22*t2);
    float dx = pwx - twx, dy = pwy - twy, dz = pwz - twz;
    float dn = rsqrtf(dx*dx + dy*dy + dz*dz);
    float x = dx*dn, y = dy*dn, z = dz*dn;
    float xx = x*x, yy = y*y, zz = z*z;
    float xy = x*y, yz = y*z, xz = x*z;

    float B[16];
    B[0]  = 0.28209479177387814f;
    B[1]  = -0.4886025119029199f * y;
    B[2]  =  0.4886025119029199f * z;
    B[3]  = -0.4886025119029199f * x;
    B[4]  =  1.0925484305920792f * xy;
    B[5]  = -1.0925484305920792f * yz;
    B[6]  =  0.31539156525252005f * (2.f*zz - xx - yy);
    B[7]  = -1.0925484305920792f * xz;
    B[8]  =  0.5462742152960396f * (xx - yy);
    B[9]  = -0.5900435899266435f * y * (3.f*xx - yy);
    B[10] =  2.890611442640554f  * xy * z;
    B[11] = -0.4570457994644658f * y * (4.f*zz - xx - yy);
    B[12] =  0.3731763325901154f * z * (2.f*zz - 3.f*xx - 3.f*yy);
    B[13] = -0.4570457994644658f * x * (4.f*zz - xx - yy);
    B[14] =  1.445305721320277f  * z * (xx - yy);
    B[15] = -0.5900435899266435f * x * (xx - 3.f*yy);

    float col[3];
    #pragma unroll
    for (int c = 0; c < 3; c++) {
        float v = B[0] * low_shs[3*i + c];
        #pragma unroll
        for (int j = 1; j < 16; j++)
            v += B[j] * high_shs[45*i + 3*(j-1) + c];
        col[c] = fmaxf(v + 0.5f, 0.0f);
    }

    g_depth[i] = depth;
    g_pre[3*i+0] = make_float4(ux, uy, cc*inv, -b*inv);
    g_pre[3*i+1] = make_float4(a*inv, alpha, col[0], col[1]);
    g_pre[3*i+2] = make_float4(col[2], 0.f, 0.f, 0.f);

    if (write_areas) {
        areas[2*i+0] = radius;
        areas[2*i+1] = radius;
    }
}

// ============================================================
// Kernel 2: bitonic sort by depth (single block) + gather
// ============================================================
__global__ void sort_gather_kernel()
{
    __shared__ float          sk[NG];
    __shared__ unsigned short sv[NG];
    int tid = threadIdx.x;

    for (int i = tid; i < NG; i += 1024) { sk[i] = g_depth[i]; sv[i] = (unsigned short)i; }
    __syncthreads();

    for (int k = 2; k <= NG; k <<= 1) {
        for (int j = k >> 1; j > 0; j >>= 1) {
            for (int i = tid; i < NG; i += 1024) {
                int l = i ^ j;
                if (l > i) {
                    bool asc = ((i & k) == 0);
                    float va = sk[i], vb = sk[l];
                    if (asc ? (va > vb) : (va < vb)) {
                        sk[i] = vb; sk[l] = va;
                        unsigned short t = sv[i]; sv[i] = sv[l]; sv[l] = t;
                    }
                }
            }
            __syncthreads();
        }
    }

    for (int i = tid; i < NG; i += 1024) {
        int s = sv[i];
        g_sorted[3*i+0] = g_pre[3*s+0];
        g_sorted[3*i+1] = g_pre[3*s+1];
        g_sorted[3*i+2] = g_pre[3*s+2];
    }
}

// ============================================================
// Kernel 3: rasterize — one warp per pixel, warp-parallel
// chunks of 32 gaussians with prefix-product transmittance.
// ============================================================
__global__ void raster_kernel(float* __restrict__ img)
{
    int gwarp = (blockIdx.x * blockDim.x + threadIdx.x) >> 5;
    int lane  = threadIdx.x & 31;
    if (gwarp >= NPIX) return;

    float px = (float)(gwarp % WI);
    float py = (float)(gwarp / WI);

    float T = 1.0f;
    float cr = 0.f, cg = 0.f, cb = 0.f;
    const float* gs = (const float*)g_sorted;

    for (int base = 0; base < NG; base += 32) {
        int g = base + lane;
        float4 f0 = g_sorted[3*g+0];
        float4 f1 = g_sorted[3*g+1];
        float  bB = gs[12*g + 8];

        float dx = f0.x - px, dy = f0.y - py;
        float power = -0.5f * (f0.z*dx*dx + f1.x*dy*dy) - f0.w*dx*dy;
        float ap = f1.y * __expf(fminf(power, 0.0f));
        ap = fminf(ap, 0.99f);
        if (ap < (1.0f/255.0f)) ap = 0.0f;

        float t = 1.0f - ap;
        // inclusive prefix product of t across the warp
        float p = t;
        #pragma unroll
        for (int d = 1; d < 32; d <<= 1) {
            float o = __shfl_up_sync(0xffffffffu, p, d);
            if (lane >= d) p *= o;
        }
        float excl = __shfl_up_sync(0xffffffffu, p, 1);
        if (lane == 0) excl = 1.0f;

        float tau = T * excl;
        float w = (tau > 1e-4f) ? ap * tau : 0.0f;
        cr += w * f1.z;
        cg += w * f1.w;
        cb += w * bB;

        T *= __shfl_sync(0xffffffffu, p, 31);   // warp-uniform
        if (T <= 1e-4f) break;                  // exact: all later wgt == 0
    }

    #pragma unroll
    for (int d = 16; d > 0; d >>= 1) {
        cr += __shfl_xor_sync(0xffffffffu, cr, d);
        cg += __shfl_xor_sync(0xffffffffu, cg, d);
        cb += __shfl_xor_sync(0xffffffffu, cb, d);
    }
    if (lane == 0) {
        img[0*NPIX + gwarp] = cr;
        img[1*NPIX + gwarp] = cg;
        img[2*NPIX + gwarp] = cb;
    }
}

// ============================================================
extern "C" void kernel_launch(void* const* d_in, const int* in_sizes, int n_in,
                              void* d_out, int out_size)
{
    const float* pws        = (const float*)d_in[0];
    const float* low_shs    = (const float*)d_in[1];
    const float* high_shs   = (const float*)d_in[2];
    const float* alphas_raw = (const float*)d_in[3];
    const float* scales_raw = (const float*)d_in[4];
    const float* rots_raw   = (const float*)d_in[5];
    // d_in[6] = us (unused by reference)
    const float* Rcw        = (const float*)d_in[7];
    const float* tcw        = (const float*)d_in[8];
    const float* cam        = (const float*)d_in[9];

    float* out   = (float*)d_out;
    int write_areas = (out_size >= 3*NPIX + 2*NG) ? 1 : 0;
    float* areas = out + 3*NPIX;

    preprocess_kernel<<<NG/256, 256>>>(pws, low_shs, high_shs, alphas_raw,
                                       scales_raw, rots_raw, Rcw, tcw, cam,
                                       areas, write_areas);
    sort_gather_kernel<<<1, 1024>>>();
    raster_kernel<<<(NPIX*32)/256, 256>>>(out);
}

// round 2
// speedup vs baseline: 1.3032x; 1.3032x over previous
#include <cuda_runtime.h>

#define NG   4096
#define WI   96
#define HI   96
#define NPIX (WI*HI)
#define TS   8            // tile size in px
#define TGX  (WI/TS)      // 12
#define TGY  (HI/TS)      // 12

// ---- device scratch ----
__device__ float  g_depth[NG];
__device__ float4 g_pre0[NG];    // ux, uy, cinv0, cinv1
__device__ float4 g_pre1[NG];    // cinv2, alpha, R, G
__device__ float  g_preB[NG];    // B
__device__ float4 g_prebb[NG];   // xmin, xmax, ymin, ymax
__device__ float4 g_s0[NG];
__device__ float4 g_s1[NG];
__device__ float  g_sB[NG];
__device__ float4 g_sbb[NG];

// ============================================================
// Kernel 1: per-gaussian preprocessing
// ============================================================
__global__ void preprocess_kernel(
    const float* __restrict__ pws,
    const float* __restrict__ low_shs,
    const float* __restrict__ high_shs,
    const float* __restrict__ alphas_raw,
    const float* __restrict__ scales_raw,
    const float* __restrict__ rots_raw,
    const float* __restrict__ Rcw,
    const float* __restrict__ tcw,
    const float* __restrict__ cam,
    float* __restrict__ areas, int write_areas)
{
    int i = blockIdx.x * blockDim.x + threadIdx.x;
    if (i >= NG) return;

    float fx = cam[0], fy = cam[1], cx = cam[2], cy = cam[3];
    float R00=Rcw[0],R01=Rcw[1],R02=Rcw[2];
    float R10=Rcw[3],R11=Rcw[4],R12=Rcw[5];
    float R20=Rcw[6],R21=Rcw[7],R22=Rcw[8];
    float t0=tcw[0], t1=tcw[1], t2=tcw[2];

    float pwx = pws[3*i+0], pwy = pws[3*i+1], pwz = pws[3*i+2];

    float pcx = R00*pwx + R01*pwy + R02*pwz + t0;
    float pcy = R10*pwx + R11*pwy + R12*pwz + t1;
    float pcz = R20*pwx + R21*pwy + R22*pwz + t2;
    float depth = pcz;
    float zs = depth > 1e-6f ? depth : 1e-6f;
    float invz = 1.0f / zs;

    float ux = fx * pcx * invz + cx;
    float uy = fy * pcy * invz + cy;

    float qw = rots_raw[4*i+0], qx = rots_raw[4*i+1];
    float qy = rots_raw[4*i+2], qz = rots_raw[4*i+3];
    float qn = rsqrtf(qw*qw + qx*qx + qy*qy + qz*qz);
    qw*=qn; qx*=qn; qy*=qn; qz*=qn;

    float s0 = expf(scales_raw[3*i+0]);
    float s1 = expf(scales_raw[3*i+1]);
    float s2 = expf(scales_raw[3*i+2]);

    float r00 = 1.f - 2.f*(qy*qy + qz*qz), r01 = 2.f*(qx*qy - qw*qz), r02 = 2.f*(qx*qz + qw*qy);
    float r10 = 2.f*(qx*qy + qw*qz), r11 = 1.f - 2.f*(qx*qx + qz*qz), r12 = 2.f*(qy*qz - qw*qx);
    float r20 = 2.f*(qx*qz - qw*qy), r21 = 2.f*(qy*qz + qw*qx), r22 = 1.f - 2.f*(qx*qx + qy*qy);

    float m00=r00*s0, m01=r01*s1, m02=r02*s2;
    float m10=r10*s0, m11=r11*s1, m12=r12*s2;
    float m20=r20*s0, m21=r21*s1, m22=r22*s2;

    float limx = 1.3f * ((float)WI / (2.0f*fx));
    float limy = 1.3f * ((float)HI / (2.0f*fy));
    float txc = fminf(fmaxf(pcx*invz, -limx), limx) * zs;
    float tyc = fminf(fmaxf(pcy*invz, -limy), limy) * zs;
    float j00 = fx*invz,  j02 = -fx*txc*invz*invz;
    float j11 = fy*invz,  j12 = -fy*tyc*invz*invz;

    float T00 = j00*R00 + j02*R20, T01 = j00*R01 + j02*R21, T02 = j00*R02 + j02*R22;
    float T10 = j11*R10 + j12*R20, T11 = j11*R11 + j12*R21, T12 = j11*R12 + j12*R22;

    float W00 = T00*m00 + T01*m10 + T02*m20;
    float W01 = T00*m01 + T01*m11 + T02*m21;
    float W02 = T00*m02 + T01*m12 + T02*m22;
    float W10 = T10*m00 + T11*m10 + T12*m20;
    float W11 = T10*m01 + T11*m11 + T12*m21;
    float W12 = T10*m02 + T11*m12 + T12*m22;

    float a  = W00*W00 + W01*W01 + W02*W02 + 0.3f;
    float b  = W00*W10 + W01*W11 + W02*W12;
    float cc = W10*W10 + W11*W11 + W12*W12 + 0.3f;
    float det = a*cc - b*b;
    float inv = 1.0f / det;

    float mid = 0.5f*(a + cc);
    float lam = mid + sqrtf(fmaxf(mid*mid - det, 0.1f));
    float radius = ceilf(3.0f * sqrtf(lam));

    float alpha = 1.0f / (1.0f + expf(-alphas_raw[i]));
    if (!(depth > 0.2f)) alpha = 0.0f;

    float twx = -(R00*t0 + R10*t1 + R20*t2);
    float twy = -(R01*t0 + R11*t1 + R21*t2);
    float twz = -(R02*t0 + R12*t1 + R22*t2);
    float dx = pwx - twx, dy = pwy - twy, dz = pwz - twz;
    float dn = rsqrtf(dx*dx + dy*dy + dz*dz);
    float x = dx*dn, y = dy*dn, z = dz*dn;
    float xx = x*x, yy = y*y, zz = z*z;
    float xy = x*y, yz = y*z, xz = x*z;

    float B[16];
    B[0]  = 0.28209479177387814f;
    B[1]  = -0.4886025119029199f * y;
    B[2]  =  0.4886025119029199f * z;
    B[3]  = -0.4886025119029199f * x;
    B[4]  =  1.0925484305920792f * xy;
    B[5]  = -1.0925484305920792f * yz;
    B[6]  =  0.31539156525252005f * (2.f*zz - xx - yy);
    B[7]  = -1.0925484305920792f * xz;
    B[8]  =  0.5462742152960396f * (xx - yy);
    B[9]  = -0.5900435899266435f * y * (3.f*xx - yy);
    B[10] =  2.890611442640554f  * xy * z;
    B[11] = -0.4570457994644658f * y * (4.f*zz - xx - yy);
    B[12] =  0.3731763325901154f * z * (2.f*zz - 3.f*xx - 3.f*yy);
    B[13] = -0.4570457994644658f * x * (4.f*zz - xx - yy);
    B[14] =  1.445305721320277f  * z * (xx - yy);
    B[15] = -0.5900435899266435f * x * (xx - 3.f*yy);

    float col[3];
    #pragma unroll
    for (int c = 0; c < 3; c++) {
        float v = B[0] * low_shs[3*i + c];
        #pragma unroll
        for (int j = 1; j < 16; j++)
            v += B[j] * high_shs[45*i + 3*(j-1) + c];
        col[c] = fmaxf(v + 0.5f, 0.0f);
    }

    // exact cull bbox: ap = alpha*exp(-q/2) >= 1/255 requires q <= 2 ln(255 alpha)
    float4 bb;
    if (alpha * 255.0f <= 1.0f) {
        bb = make_float4(1e9f, -1e9f, 1e9f, -1e9f);     // never contributes
    } else {
        float qcut = 2.0f * logf(255.0f * alpha) * 1.0001f;  // tiny safety margin
        float ex = sqrtf(qcut * a);
        float ey = sqrtf(qcut * cc);
        bb = make_float4(ux - ex, ux + ex, uy - ey, uy + ey);
    }

    g_depth[i] = depth;
    g_pre0[i] = make_float4(ux, uy, cc*inv, -b*inv);
    g_pre1[i] = make_float4(a*inv, alpha, col[0], col[1]);
    g_preB[i] = col[2];
    g_prebb[i] = bb;

    if (write_areas) {
        areas[2*i+0] = radius;
        areas[2*i+1] = radius;
    }
}

// ============================================================
// Kernel 2: bitonic sort by depth (single block) + gather
// ============================================================
__global__ void sort_gather_kernel()
{
    __shared__ float          sk[NG];
    __shared__ unsigned short sv[NG];
    int tid = threadIdx.x;

    for (int i = tid; i < NG; i += 1024) { sk[i] = g_depth[i]; sv[i] = (unsigned short)i; }
    __syncthreads();

    for (int k = 2; k <= NG; k <<= 1) {
        for (int j = k >> 1; j > 0; j >>= 1) {
            for (int i = tid; i < NG; i += 1024) {
                int l = i ^ j;
                if (l > i) {
                    bool asc = ((i & k) == 0);
                    float va = sk[i], vb = sk[l];
                    if (asc ? (va > vb) : (va < vb)) {
                        sk[i] = vb; sk[l] = va;
                        unsigned short t = sv[i]; sv[i] = sv[l]; sv[l] = t;
                    }
                }
            }
            __syncthreads();
        }
    }

    for (int i = tid; i < NG; i += 1024) {
        int s = sv[i];
        g_s0[i]  = g_pre0[s];
        g_s1[i]  = g_pre1[s];
        g_sB[i]  = g_preB[s];
        g_sbb[i] = g_prebb[s];
    }
}

// ============================================================
// Kernel 3: tiled rasterizer — one 8x8-px tile per 64-thread
// block; ballot-compacted, depth-ordered survivor batches.
// ============================================================
__global__ void raster_kernel(float* __restrict__ img)
{
    __shared__ float4 s_f0[64];
    __shared__ float4 s_f1[64];
    __shared__ float  s_B[64];
    __shared__ int    s_list[64];
    __shared__ int    s_wc[2];

    int tid  = threadIdx.x;
    int lane = tid & 31;
    int wrp  = tid >> 5;

    int tx0 = blockIdx.x * TS;
    int ty0 = blockIdx.y * TS;
    float px = (float)(tx0 + (tid & 7));
    float py = (float)(ty0 + (tid >> 3));

    float tile_xmin = (float)tx0,        tile_ymin = (float)ty0;
    float tile_xmax = (float)(tx0+TS-1), tile_ymax = (float)(ty0+TS-1);

    float T = 1.0f;
    float cr = 0.f, cg = 0.f, cb = 0.f;

    for (int base = 0; base < NG; base += 64) {
        // ---- cull batch of 64 gaussians against this tile ----
        int g = base + tid;
        float4 bb = g_sbb[g];
        bool hit = (bb.x <= tile_xmax) && (bb.y >= tile_xmin) &&
                   (bb.z <= tile_ymax) && (bb.w >= tile_ymin);
        unsigned m = __ballot_sync(0xffffffffu, hit);
        if (lane == 0) s_wc[wrp] = __popc(m);
        __syncthreads();
        int n = s_wc[0] + s_wc[1];
        if (n > 0) {
            int off = (wrp == 1) ? s_wc[0] : 0;
            int pos = off + __popc(m & ((1u << lane) - 1u));
            if (hit) s_list[pos] = g;
            __syncthreads();
            if (tid < n) {
                int s = s_list[tid];
                s_f0[tid] = g_s0[s];
                s_f1[tid] = g_s1[s];
                s_B[tid]  = g_sB[s];
            }
        }
        __syncthreads();

        // ---- sequential per-pixel blend over survivors ----
        bool active = (T > 1e-4f);
        if (active) {
            for (int j = 0; j < n; j++) {
                float4 f0 = s_f0[j];
                float4 f1 = s_f1[j];
                float dx = f0.x - px, dy = f0.y - py;
                float power = -0.5f * (f0.z*dx*dx + f1.x*dy*dy) - f0.w*dx*dy;
                float ap = f1.y * __expf(fminf(power, 0.0f));
                ap = fminf(ap, 0.99f);
                if (ap >= (1.0f/255.0f)) {
                    float w = (T > 1e-4f) ? ap * T : 0.0f;
                    cr += w * f1.z;
                    cg += w * f1.w;
                    cb += w * s_B[j];
                    T *= (1.0f - ap);
                }
            }
        }
        // block-uniform early exit once every pixel is saturated
        if (__syncthreads_count(T > 1e-4f) == 0) break;
    }

    int pix = (ty0 + (tid >> 3)) * WI + (tx0 + (tid & 7));
    img[0*NPIX + pix] = cr;
    img[1*NPIX + pix] = cg;
    img[2*NPIX + pix] = cb;
}

// ============================================================
extern "C" void kernel_launch(void* const* d_in, const int* in_sizes, int n_in,
                              void* d_out, int out_size)
{
    const float* pws        = (const float*)d_in[0];
    const float* low_shs    = (const float*)d_in[1];
    const float* high_shs   = (const float*)d_in[2];
    const float* alphas_raw = (const float*)d_in[3];
    const float* scales_raw = (const float*)d_in[4];
    const float* rots_raw   = (const float*)d_in[5];
    // d_in[6] = us (unused)
    const float* Rcw        = (const float*)d_in[7];
    const float* tcw        = (const float*)d_in[8];
    const float* cam        = (const float*)d_in[9];

    float* out   = (float*)d_out;
    int write_areas = (out_size >= 3*NPIX + 2*NG) ? 1 : 0;
    float* areas = out + 3*NPIX;

    preprocess_kernel<<<NG/256, 256>>>(pws, low_shs, high_shs, alphas_raw,
                                       scales_raw, rots_raw, Rcw, tcw, cam,
                                       areas, write_areas);
    sort_gather_kernel<<<1, 1024>>>();
    dim3 rgrid(TGX, TGY);
    raster_kernel<<<rgrid, 64>>>(out);
}

// round 3
// speedup vs baseline: 3.2531x; 2.4963x over previous
#include <cuda_runtime.h>

#define NG   4096
#define WI   96
#define HI   96
#define NPIX (WI*HI)
#define TS   8            // tile size in px
#define TGX  (WI/TS)      // 12
#define TGY  (HI/TS)      // 12

// ---- device scratch ----
__device__ float  g_depth[NG];
__device__ float4 g_pre0[NG];    // ux, uy, cinv0, cinv1
__device__ float4 g_pre1[NG];    // cinv2, alpha, R, G
__device__ float  g_preB[NG];    // B
__device__ float4 g_prebb[NG];   // xmin, xmax, ymin, ymax
__device__ float4 g_s0[NG];
__device__ float4 g_s1[NG];
__device__ float  g_sB[NG];
__device__ float4 g_sbb[NG];

// ============================================================
// Kernel 1: per-gaussian preprocessing
// ============================================================
__global__ void preprocess_kernel(
    const float* __restrict__ pws,
    const float* __restrict__ low_shs,
    const float* __restrict__ high_shs,
    const float* __restrict__ alphas_raw,
    const float* __restrict__ scales_raw,
    const float* __restrict__ rots_raw,
    const float* __restrict__ Rcw,
    const float* __restrict__ tcw,
    const float* __restrict__ cam,
    float* __restrict__ areas, int write_areas)
{
    int i = blockIdx.x * blockDim.x + threadIdx.x;
    if (i >= NG) return;

    float fx = cam[0], fy = cam[1], cx = cam[2], cy = cam[3];
    float R00=Rcw[0],R01=Rcw[1],R02=Rcw[2];
    float R10=Rcw[3],R11=Rcw[4],R12=Rcw[5];
    float R20=Rcw[6],R21=Rcw[7],R22=Rcw[8];
    float t0=tcw[0], t1=tcw[1], t2=tcw[2];

    float pwx = pws[3*i+0], pwy = pws[3*i+1], pwz = pws[3*i+2];

    float pcx = R00*pwx + R01*pwy + R02*pwz + t0;
    float pcy = R10*pwx + R11*pwy + R12*pwz + t1;
    float pcz = R20*pwx + R21*pwy + R22*pwz + t2;
    float depth = pcz;
    float zs = depth > 1e-6f ? depth : 1e-6f;
    float invz = 1.0f / zs;

    float ux = fx * pcx * invz + cx;
    float uy = fy * pcy * invz + cy;

    float qw = rots_raw[4*i+0], qx = rots_raw[4*i+1];
    float qy = rots_raw[4*i+2], qz = rots_raw[4*i+3];
    float qn = rsqrtf(qw*qw + qx*qx + qy*qy + qz*qz);
    qw*=qn; qx*=qn; qy*=qn; qz*=qn;

    float s0 = expf(scales_raw[3*i+0]);
    float s1 = expf(scales_raw[3*i+1]);
    float s2 = expf(scales_raw[3*i+2]);

    float r00 = 1.f - 2.f*(qy*qy + qz*qz), r01 = 2.f*(qx*qy - qw*qz), r02 = 2.f*(qx*qz + qw*qy);
    float r10 = 2.f*(qx*qy + qw*qz), r11 = 1.f - 2.f*(qx*qx + qz*qz), r12 = 2.f*(qy*qz - qw*qx);
    float r20 = 2.f*(qx*qz - qw*qy), r21 = 2.f*(qy*qz + qw*qx), r22 = 1.f - 2.f*(qx*qx + qy*qy);

    float m00=r00*s0, m01=r01*s1, m02=r02*s2;
    float m10=r10*s0, m11=r11*s1, m12=r12*s2;
    float m20=r20*s0, m21=r21*s1, m22=r22*s2;

    float limx = 1.3f * ((float)WI / (2.0f*fx));
    float limy = 1.3f * ((float)HI / (2.0f*fy));
    float txc = fminf(fmaxf(pcx*invz, -limx), limx) * zs;
    float tyc = fminf(fmaxf(pcy*invz, -limy), limy) * zs;
    float j00 = fx*invz,  j02 = -fx*txc*invz*invz;
    float j11 = fy*invz,  j12 = -fy*tyc*invz*invz;

    float T00 = j00*R00 + j02*R20, T01 = j00*R01 + j02*R21, T02 = j00*R02 + j02*R22;
    float T10 = j11*R10 + j12*R20, T11 = j11*R11 + j12*R21, T12 = j11*R12 + j12*R22;

    float W00 = T00*m00 + T01*m10 + T02*m20;
    float W01 = T00*m01 + T01*m11 + T02*m21;
    float W02 = T00*m02 + T01*m12 + T02*m22;
    float W10 = T10*m00 + T11*m10 + T12*m20;
    float W11 = T10*m01 + T11*m11 + T12*m21;
    float W12 = T10*m02 + T11*m12 + T12*m22;

    float a  = W00*W00 + W01*W01 + W02*W02 + 0.3f;
    float b  = W00*W10 + W01*W11 + W02*W12;
    float cc = W10*W10 + W11*W11 + W12*W12 + 0.3f;
    float det = a*cc - b*b;
    float inv = 1.0f / det;

    float mid = 0.5f*(a + cc);
    float lam = mid + sqrtf(fmaxf(mid*mid - det, 0.1f));
    float radius = ceilf(3.0f * sqrtf(lam));

    float alpha = 1.0f / (1.0f + expf(-alphas_raw[i]));
    if (!(depth > 0.2f)) alpha = 0.0f;

    float twx = -(R00*t0 + R10*t1 + R20*t2);
    float twy = -(R01*t0 + R11*t1 + R21*t2);
    float twz = -(R02*t0 + R12*t1 + R22*t2);
    float dx = pwx - twx, dy = pwy - twy, dz = pwz - twz;
    float dn = rsqrtf(dx*dx + dy*dy + dz*dz);
    float x = dx*dn, y = dy*dn, z = dz*dn;
    float xx = x*x, yy = y*y, zz = z*z;
    float xy = x*y, yz = y*z, xz = x*z;

    float B[16];
    B[0]  = 0.28209479177387814f;
    B[1]  = -0.4886025119029199f * y;
    B[2]  =  0.4886025119029199f * z;
    B[3]  = -0.4886025119029199f * x;
    B[4]  =  1.0925484305920792f * xy;
    B[5]  = -1.0925484305920792f * yz;
    B[6]  =  0.31539156525252005f * (2.f*zz - xx - yy);
    B[7]  = -1.0925484305920792f * xz;
    B[8]  =  0.5462742152960396f * (xx - yy);
    B[9]  = -0.5900435899266435f * y * (3.f*xx - yy);
    B[10] =  2.890611442640554f  * xy * z;
    B[11] = -0.4570457994644658f * y * (4.f*zz - xx - yy);
    B[12] =  0.3731763325901154f * z * (2.f*zz - 3.f*xx - 3.f*yy);
    B[13] = -0.4570457994644658f * x * (4.f*zz - xx - yy);
    B[14] =  1.445305721320277f  * z * (xx - yy);
    B[15] = -0.5900435899266435f * x * (xx - 3.f*yy);

    float col[3];
    #pragma unroll
    for (int c = 0; c < 3; c++) {
        float v = B[0] * low_shs[3*i + c];
        #pragma unroll
        for (int j = 1; j < 16; j++)
            v += B[j] * high_shs[45*i + 3*(j-1) + c];
        col[c] = fmaxf(v + 0.5f, 0.0f);
    }

    // exact cull bbox: ap = alpha*exp(-q/2) >= 1/255 requires q <= 2 ln(255 alpha)
    float4 bb;
    if (alpha * 255.0f <= 1.0f) {
        bb = make_float4(1e9f, -1e9f, 1e9f, -1e9f);     // never contributes
    } else {
        float qcut = 2.0f * logf(255.0f * alpha) * 1.0001f;
        float ex = sqrtf(qcut * a);
        float ey = sqrtf(qcut * cc);
        bb = make_float4(ux - ex, ux + ex, uy - ey, uy + ey);
    }

    g_depth[i] = depth;
    g_pre0[i] = make_float4(ux, uy, cc*inv, -b*inv);
    g_pre1[i] = make_float4(a*inv, alpha, col[0], col[1]);
    g_preB[i] = col[2];
    g_prebb[i] = bb;

    if (write_areas) {
        areas[2*i+0] = radius;
        areas[2*i+1] = radius;
    }
}

// ============================================================
// Kernel 2: chip-wide stable rank sort + scatter.
// One warp per gaussian; depths staged in shared memory.
// rank(i) = #{ j : d[j] < d[i]  or  (d[j]==d[i] and j<i) }
// (exactly matches stable jnp.argsort)
// ============================================================
__global__ void rank_scatter_kernel()
{
    __shared__ float s_d[NG];
    int tid  = threadIdx.x;
    int lane = tid & 31;
    int wrp  = tid >> 5;
    int i    = blockIdx.x * 8 + wrp;      // gaussian handled by this warp

    for (int j = tid; j < NG; j += 256) s_d[j] = g_depth[j];
    __syncthreads();

    float di = s_d[i];
    int cnt = 0;
    #pragma unroll 4
    for (int j = lane; j < NG; j += 32) {
        float dj = s_d[j];
        cnt += (dj < di) || (dj == di && j < i);
    }
    #pragma unroll
    for (int d = 16; d > 0; d >>= 1)
        cnt += __shfl_xor_sync(0xffffffffu, cnt, d);
    int r = cnt;   // all lanes agree

    if      (lane == 0) g_s0[r]  = g_pre0[i];
    else if (lane == 1) g_s1[r]  = g_pre1[i];
    else if (lane == 2) g_sB[r]  = g_preB[i];
    else if (lane == 3) g_sbb[r] = g_prebb[i];
}

// ============================================================
// Kernel 3: tiled rasterizer — one 8x8-px tile per 256-thread
// block; 256-wide cull batches, ordered compaction, 64-pixel blend.
// ============================================================
__global__ void raster_kernel(float* __restrict__ img)
{
    __shared__ float4 s_f0[256];
    __shared__ float4 s_f1[256];
    __shared__ float  s_B[256];
    __shared__ int    s_list[256];
    __shared__ int    s_wcnt[8];
    __shared__ int    s_woff[8];
    __shared__ int    s_n;

    int tid  = threadIdx.x;
    int lane = tid & 31;
    int wrp  = tid >> 5;

    int tx0 = blockIdx.x * TS;
    int ty0 = blockIdx.y * TS;
    float px = (float)(tx0 + (tid & 7));
    float py = (float)(ty0 + (tid >> 3));

    float tile_xmin = (float)tx0,        tile_ymin = (float)ty0;
    float tile_xmax = (float)(tx0+TS-1), tile_ymax = (float)(ty0+TS-1);

    float T = (tid < 64) ? 1.0f : 0.0f;   // phantom threads contribute 0 to exit count
    float cr = 0.f, cg = 0.f, cb = 0.f;

    for (int base = 0; base < NG; base += 256) {
        // ---- cull batch of 256 gaussians against this tile ----
        int g = base + tid;
        float4 bb = g_sbb[g];
        bool hit = (bb.x <= tile_xmax) && (bb.y >= tile_xmin) &&
                   (bb.z <= tile_ymax) && (bb.w >= tile_ymin);
        unsigned m = __ballot_sync(0xffffffffu, hit);
        if (lane == 0) s_wcnt[wrp] = __popc(m);
        __syncthreads();
        if (tid == 0) {
            int s = 0;
            #pragma unroll
            for (int k = 0; k < 8; k++) { s_woff[k] = s; s += s_wcnt[k]; }
            s_n = s;
        }
        __syncthreads();
        int n = s_n;
        if (n > 0) {
            if (hit) s_list[s_woff[wrp] + __popc(m & ((1u << lane) - 1u))] = g;
            __syncthreads();
            if (tid < n) {
                int s = s_list[tid];
                s_f0[tid] = g_s0[s];
                s_f1[tid] = g_s1[s];
                s_B[tid]  = g_sB[s];
            }
        }
        __syncthreads();

        // ---- sequential per-pixel blend over survivors (64 px threads) ----
        if (tid < 64 && T > 1e-4f) {
            for (int j = 0; j < n; j++) {
                float4 f0 = s_f0[j];
                float4 f1 = s_f1[j];
                float dx = f0.x - px, dy = f0.y - py;
                float power = -0.5f * (f0.z*dx*dx + f1.x*dy*dy) - f0.w*dx*dy;
                float ap = f1.y * __expf(fminf(power, 0.0f));
                ap = fminf(ap, 0.99f);
                if (ap >= (1.0f/255.0f)) {
                    float w = (T > 1e-4f) ? ap * T : 0.0f;
                    cr += w * f1.z;
                    cg += w * f1.w;
                    cb += w * s_B[j];
                    T *= (1.0f - ap);
                }
            }
        }
        if (__syncthreads_count(T > 1e-4f) == 0) break;
    }

    if (tid < 64) {
        int pix = (ty0 + (tid >> 3)) * WI + (tx0 + (tid & 7));
        img[0*NPIX + pix] = cr;
        img[1*NPIX + pix] = cg;
        img[2*NPIX + pix] = cb;
    }
}

// ============================================================
extern "C" void kernel_launch(void* const* d_in, const int* in_sizes, int n_in,
                              void* d_out, int out_size)
{
    const float* pws        = (const float*)d_in[0];
    const float* low_shs    = (const float*)d_in[1];
    const float* high_shs   = (const float*)d_in[2];
    const float* alphas_raw = (const float*)d_in[3];
    const float* scales_raw = (const float*)d_in[4];
    const float* rots_raw   = (const float*)d_in[5];
    // d_in[6] = us (unused)
    const float* Rcw        = (const float*)d_in[7];
    const float* tcw        = (const float*)d_in[8];
    const float* cam        = (const float*)d_in[9];

    float* out   = (float*)d_out;
    int write_areas = (out_size >= 3*NPIX + 2*NG) ? 1 : 0;
    float* areas = out + 3*NPIX;

    preprocess_kernel<<<NG/64, 64>>>(pws, low_shs, high_shs, alphas_raw,
                                     scales_raw, rots_raw, Rcw, tcw, cam,
                                     areas, write_areas);
    rank_scatter_kernel<<<NG/8, 256>>>();
    dim3 rgrid(TGX, TGY);
    raster_kernel<<<rgrid, 256>>>(out);
}